// round 9
// baseline (speedup 1.0000x reference)
#include <cuda_runtime.h>
#include <math.h>

// Problem constants
#define Bn   32
#define Nn   256
#define Hn   64
#define EPSf 1e-6f

// Table in s = d^2 space: KI intervals over [0, SMAX]; one float4 cubic each.
#define KI    1024
#define SMAXf 128.0f

// Persistent-kernel shape: all blocks co-resident (128 <= 148 SMs)
#define NB 128
#define NT 1024

// Device scratch (zero-init; restored each launch -> graph-replay safe)
__device__ float4   g_tab[KI];
__device__ float    g_v[Bn * Nn * 3];
__device__ float    g_bsum[Bn * 4];
__device__ unsigned g_ticket[Bn];
__device__ unsigned g_bar_cnt;
__device__ unsigned g_bar_gen;

__device__ __forceinline__ void grid_barrier0()
{
    __syncthreads();
    if (threadIdx.x == 0) {
        __threadfence();
        volatile unsigned* genp = &g_bar_gen;
        unsigned gen = *genp;
        unsigned tkt = atomicAdd(&g_bar_cnt, 1u);
        if (tkt == NB - 1) {
            atomicExch(&g_bar_cnt, 0u);
            __threadfence();
            atomicAdd(&g_bar_gen, 1u);
        } else {
            while (*genp == gen) { __nanosleep(64); }
        }
        __threadfence();
    }
    __syncthreads();
}

__device__ __forceinline__ float fast_tanh(float z)
{
    float az = fabsf(z);
    float e  = __expf(-2.f * az);
    float t  = __fdividef(1.f - e, 1.f + e);
    return copysignf(t, z);
}

// ---------------------------------------------------------------------------
__global__ void __launch_bounds__(NT, 1)
fused_kernel(const float* __restrict__ t_in,
             const float* __restrict__ x,
             const float* __restrict__ W1,   // (2,64)
             const float* __restrict__ b1,   // (64)
             const float* __restrict__ W2,   // (64,64)
             const float* __restrict__ b2,   // (64)
             const float* __restrict__ W3,   // (64,1)
             const float* __restrict__ b3,   // (1)
             float*       __restrict__ out)
{
    const int tid = threadIdx.x;
    const int blk = blockIdx.x;

    __shared__ float    sW2[Hn * Hn];    // 16 KB (phase A only)
    __shared__ float4   stab[KI];        // 16 KB (phase B table)
    __shared__ float2   sh1[11][Hn];     // layer-1 (h1, dh1/dd) per slot
    __shared__ float2   s_node[11];      // (f, f'(d)) at nodes/subnodes
    __shared__ float    s_red[11][2][2];
    __shared__ float4   sxs4[Nn];        // positions, padded float4
    __shared__ float    s_wpart[32][4];
    __shared__ unsigned s_tk;
    __shared__ float    s_m[4];

    const float hstep = SMAXf / (float)KI;       // s-spacing (0.125)
    const float inv_h = (float)KI / SMAXf;       // 8
    const float Gc    = 2.f * inv_h;             // for F'(s) from dP/dw

    const int b     = blk >> 2;
    const int ibase = (blk & 3) * 64;

    // =========================== Phase A: table ===========================
    {
        // stage positions -> padded float4
        if (tid < Nn) {
            const float* xb = x + b * Nn * 3 + tid * 3;
            sxs4[tid] = make_float4(xb[0], xb[1], xb[2], 0.f);
        }

        reinterpret_cast<float4*>(sW2)[tid] =
            reinterpret_cast<const float4*>(W2)[tid];

        const int  slot   = tid >> 6;     // 0..15
        const int  p      = tid & 63;
        const bool active = (slot < 9) || (blk == 0 && slot < 11);

        // node abscissa in d-space
        float dval = 0.f;
        if (slot < 9)       dval = sqrtf((float)(blk * 8 + slot) * hstep);
        else if (slot == 9) dval = sqrtf(hstep * (1.f / 9.f));
        else                dval = sqrtf(hstep * (4.f / 9.f));

        const float t = t_in[0];

        if (active) {
            float w0 = W1[p];
            float z  = fmaf(dval, w0, fmaf(t, W1[64 + p], b1[p]));
            float h1 = fast_tanh(z);
            float e1 = 1.f - h1 * h1;
            sh1[slot][p] = make_float2(h1, e1 * w0);
        }
        __syncthreads();

        float pf = 0.f, pfp = 0.f;
        if (active) {
            float s  = b2[p];
            float sd = 0.f;
#pragma unroll 8
            for (int l = 0; l < Hn; l++) {
                float  w2 = sW2[l * 64 + p];
                float2 hv = sh1[slot][l];
                s  = fmaf(w2, hv.x, s);
                sd = fmaf(w2, hv.y, sd);
            }
            float h2 = fast_tanh(s);
            float e2 = 1.f - h2 * h2;
            float w3 = W3[p];
            pf  = w3 * h2;          // f at this node
            pfp = w3 * e2 * sd;     // f'(d) at this node
        }

        const unsigned FULL = 0xffffffffu;
#pragma unroll
        for (int off = 16; off; off >>= 1) {
            pf  += __shfl_down_sync(FULL, pf,  off);
            pfp += __shfl_down_sync(FULL, pfp, off);
        }
        if (active && (p & 31) == 0) {
            int ws = p >> 5;
            s_red[slot][ws][0] = pf;
            s_red[slot][ws][1] = pfp;
        }
        __syncthreads();
        if (active && p == 0) {
            s_node[slot] = make_float2(
                s_red[slot][0][0] + s_red[slot][1][0] + b3[0],
                s_red[slot][0][1] + s_red[slot][1][1]);
        }
        __syncthreads();

        // build 8 intervals (threads 0..7)
        if (tid < 8) {
            int idx = blk * 8 + tid;
            if (idx == 0) {
                // Lagrange through sqrt-spaced nodes {0, h/9, 4h/9, h}
                float F0  = s_node[0].x;
                float F1s = s_node[9].x;
                float F2s = s_node[10].x;
                float F3  = s_node[1].x;
                float G1 = 729.f * (F1s - F0);
                float G2 = 729.f * (F2s - F0);
                float G3 = F3 - F0;
                float c1 = ((G1 - G3) * 0.5f - (G2 - 64.f * G3) * 0.05f) * (1.f / 27.f);
                float c2 = (G1 - G3) * 0.125f - 10.f * c1;
                float c3 = G3 - c1 - c2;
                g_tab[0] = make_float4(F0, c1, c2, c3);
            } else {
                float2 n0 = s_node[tid];
                float2 n1 = s_node[tid + 1];
                float d0 = sqrtf((float)idx * hstep);
                float d1 = sqrtf((float)(idx + 1) * hstep);
                // F'(s) = f'(d) / (2d); Hermite slopes scaled by h
                float M0 = hstep * n0.y / (2.f * d0);
                float M1 = hstep * n1.y / (2.f * d1);
                float P0 = n0.x, P1 = n1.x;
                g_tab[idx] = make_float4(
                    P0, M0,
                    3.f * (P1 - P0) - 2.f * M0 - M1,
                    2.f * (P0 - P1) + M0 + M1);
            }
        }
    }

    grid_barrier0();

    stab[tid] = g_tab[tid];              // 1024 float4, coalesced
    __syncthreads();

    // =========================== Phase B: pairs ===========================
    const int w    = tid >> 5;
    const int lane = tid & 31;
    const int iA   = ibase + w;
    const int iB   = iA + 32;

    {
        const float4 XA = sxs4[iA];
        const float4 XB = sxs4[iB];

        float cA0 = 0.f, cA1 = 0.f, cA2 = 0.f, sTA = 0.f;
        float cB0 = 0.f, cB1 = 0.f, cB2 = 0.f, sTB = 0.f;

        const float ueps = EPSf * inv_h;
        const float umax = (float)KI - 0.001f;

#pragma unroll
        for (int jj = 0; jj < 8; jj++) {
            int j = jj * 32 + lane;
            float4 XJ = sxs4[j];

            // pair (iA, j) -- no sqrt/rsqrt anywhere
            {
                float r0 = XA.x - XJ.x, r1 = XA.y - XJ.y, r2 = XA.z - XJ.z;
                float r2s = fmaf(r0, r0, fmaf(r1, r1, r2 * r2));
                float u = fminf(fmaf(r2s, inv_h, ueps), umax);
                int   k = (int)u;
                float wf = u - (float)k;
                float4 A = stab[k];
                float q  = fmaf(A.w, wf, A.z);
                float f  = fmaf(fmaf(q, wf, A.y), wf, A.x);
                float dp = fmaf(fmaf(A.w, wf, q + q), wf, A.y);  // dP/dw
                float mask = (j == iA) ? 0.f : 1.f;
                float fm = f * mask;
                cA0 = fmaf(r0, fm, cA0);
                cA1 = fmaf(r1, fm, cA1);
                cA2 = fmaf(r2, fm, cA2);
                sTA = fmaf(fmaf(dp * Gc, r2s, 3.f * f), mask, sTA);
            }
            // pair (iB, j)
            {
                float r0 = XB.x - XJ.x, r1 = XB.y - XJ.y, r2 = XB.z - XJ.z;
                float r2s = fmaf(r0, r0, fmaf(r1, r1, r2 * r2));
                float u = fminf(fmaf(r2s, inv_h, ueps), umax);
                int   k = (int)u;
                float wf = u - (float)k;
                float4 A = stab[k];
                float q  = fmaf(A.w, wf, A.z);
                float f  = fmaf(fmaf(q, wf, A.y), wf, A.x);
                float dp = fmaf(fmaf(A.w, wf, q + q), wf, A.y);
                float mask = (j == iB) ? 0.f : 1.f;
                float fm = f * mask;
                cB0 = fmaf(r0, fm, cB0);
                cB1 = fmaf(r1, fm, cB1);
                cB2 = fmaf(r2, fm, cB2);
                sTB = fmaf(fmaf(dp * Gc, r2s, 3.f * f), mask, sTB);
            }
        }

        const unsigned FULL = 0xffffffffu;
#pragma unroll
        for (int off = 16; off; off >>= 1) {
            cA0 += __shfl_down_sync(FULL, cA0, off);
            cA1 += __shfl_down_sync(FULL, cA1, off);
            cA2 += __shfl_down_sync(FULL, cA2, off);
            sTA += __shfl_down_sync(FULL, sTA, off);
            cB0 += __shfl_down_sync(FULL, cB0, off);
            cB1 += __shfl_down_sync(FULL, cB1, off);
            cB2 += __shfl_down_sync(FULL, cB2, off);
            sTB += __shfl_down_sync(FULL, sTB, off);
        }

        if (lane == 0) {
            const float invNm1 = 1.f / (float)(Nn - 1);
            float vA0 = cA0 * invNm1, vA1 = cA1 * invNm1, vA2 = cA2 * invNm1;
            float vB0 = cB0 * invNm1, vB1 = cB1 * invNm1, vB2 = cB2 * invNm1;
            float tAB = (sTA + sTB) * invNm1;

            int rA = b * Nn + iA;
            int rB = b * Nn + iB;
            g_v[rA * 3 + 0] = vA0;
            g_v[rA * 3 + 1] = vA1;
            g_v[rA * 3 + 2] = vA2;
            g_v[rB * 3 + 0] = vB0;
            g_v[rB * 3 + 1] = vB1;
            g_v[rB * 3 + 2] = vB2;

            s_wpart[w][0] = vA0 + vB0;
            s_wpart[w][1] = vA1 + vB1;
            s_wpart[w][2] = vA2 + vB2;
            s_wpart[w][3] = tAB;
        }
        __syncthreads();
        if (tid < 4) {
            float acc = 0.f;
#pragma unroll
            for (int ww = 0; ww < 32; ww++) acc += s_wpart[ww][tid];
            atomicAdd(&g_bsum[b * 4 + tid], acc);
        }
        __syncthreads();
    }

    // ===== per-batch ticket: 4th arriver finalizes this batch =====
    if (tid == 0) {
        __threadfence();
        s_tk = atomicAdd(&g_ticket[b], 1u);
        if (s_tk == 3) __threadfence();
    }
    __syncthreads();

    if (s_tk == 3) {
        if (tid < 4) s_m[tid] = g_bsum[b * 4 + tid];
        __syncthreads();

        const float invN = 1.f / (float)Nn;
        const float m0 = s_m[0] * invN;
        const float m1 = s_m[1] * invN;
        const float m2 = s_m[2] * invN;

        if (tid < Nn * 3) {
            int c = tid - (tid / 3) * 3;
            float mm = (c == 0) ? m0 : ((c == 1) ? m1 : m2);
            out[b * (Nn * 3) + tid] = g_v[b * (Nn * 3) + tid] - mm;
        }
        if (tid == 0)
            out[Bn * Nn * 3 + b] = s_m[3] * (1.f - 1.f / (float)Nn);

        __syncthreads();
        if (tid < 4) g_bsum[b * 4 + tid] = 0.f;
        if (tid == 0) g_ticket[b] = 0u;
    }
}

// ---------------------------------------------------------------------------
extern "C" void kernel_launch(void* const* d_in, const int* in_sizes, int n_in,
                              void* d_out, int out_size)
{
    const float* t  = (const float*)d_in[0];
    const float* x  = (const float*)d_in[1];
    const float* W1 = (const float*)d_in[2];
    const float* b1 = (const float*)d_in[3];
    const float* W2 = (const float*)d_in[4];
    const float* b2 = (const float*)d_in[5];
    const float* W3 = (const float*)d_in[6];
    const float* b3 = (const float*)d_in[7];

    fused_kernel<<<NB, NT>>>(t, x, W1, b1, W2, b2, W3, b3, (float*)d_out);
}

// round 10
// speedup vs baseline: 1.0020x; 1.0020x over previous
#include <cuda_runtime.h>
#include <math.h>

// Problem constants
#define Bn   32
#define Nn   256
#define Hn   64
#define EPSf 1e-6f

// Table: KI intervals in d over [0, DMAX]; one float4 f-cubic each (power basis).
#define KI    512
#define DMAXf 20.0f

// Persistent shape: 128 blocks x 512 threads (1 block/SM, 128 regs/thread budget)
#define NB 128
#define NT 512

// Device scratch (zero-init; restored each launch -> graph-replay safe)
__device__ float4   g_tab[KI];
__device__ float    g_v[Bn * Nn * 3];
__device__ float    g_bsum[Bn * 4];
__device__ unsigned g_ticket[Bn];
__device__ unsigned g_bar_cnt;
__device__ unsigned g_bar_gen;

__device__ __forceinline__ void grid_barrier0()
{
    __syncthreads();
    if (threadIdx.x == 0) {
        __threadfence();
        volatile unsigned* genp = &g_bar_gen;
        unsigned gen = *genp;
        unsigned tkt = atomicAdd(&g_bar_cnt, 1u);
        if (tkt == NB - 1) {
            atomicExch(&g_bar_cnt, 0u);
            __threadfence();
            atomicAdd(&g_bar_gen, 1u);
        } else {
            while (*genp == gen) { __nanosleep(64); }
        }
        __threadfence();
    }
    __syncthreads();
}

__device__ __forceinline__ float fast_tanh(float z)
{
    float az = fabsf(z);
    float e  = __expf(-2.f * az);
    float t  = __fdividef(1.f - e, 1.f + e);
    return copysignf(t, z);
}

// One pair: d-space cubic lookup; f' = analytic derivative of same cubic.
#define PAIR_BODY(XI, ii, c0, c1, c2, st)                                   \
    {                                                                        \
        float r0 = XI.x - XJ.x, r1 = XI.y - XJ.y, r2 = XI.z - XJ.z;          \
        float d2   = fmaf(r0, r0, fmaf(r1, r1, fmaf(r2, r2, EPSf)));         \
        float rinv = rsqrtf(d2);                                             \
        float u = fminf(d2 * rinv * inv_step, (float)KI - 0.001f);           \
        int   k = (int)u;                                                    \
        float wf = u - (float)k;                                             \
        float4 A = stab[k];                                                  \
        float q   = fmaf(A.w, wf, A.z);                                      \
        float f   = fmaf(fmaf(q, wf, A.y), wf, A.x);                         \
        float fpw = fmaf(fmaf(A.w, wf, q + q), wf, A.y);                     \
        float fp  = fpw * inv_step;                                          \
        float mask = (j == ii) ? 0.f : 1.f;                                  \
        float fm = f * mask;                                                 \
        c0 = fmaf(r0, fm, c0);                                               \
        c1 = fmaf(r1, fm, c1);                                               \
        c2 = fmaf(r2, fm, c2);                                               \
        st = fmaf(fmaf(fp * (d2 - EPSf), rinv, 3.f * f), mask, st);          \
    }

// ---------------------------------------------------------------------------
__global__ void __launch_bounds__(NT, 1)
fused_kernel(const float* __restrict__ t_in,
             const float* __restrict__ x,
             const float* __restrict__ W1,   // (2,64)
             const float* __restrict__ b1,   // (64)
             const float* __restrict__ W2,   // (64,64)
             const float* __restrict__ b2,   // (64)
             const float* __restrict__ W3,   // (64,1)
             const float* __restrict__ b3,   // (1)
             float*       __restrict__ out)
{
    const int tid = threadIdx.x;
    const int blk = blockIdx.x;

    __shared__ float    sW2[Hn * Hn];    // 16 KB (phase A)
    __shared__ float4   stab[KI];        // 8 KB  (phase B table)
    __shared__ float2   sh1[5][Hn];
    __shared__ float2   s_node[6];
    __shared__ float    s_red[5][2][2];
    __shared__ float4   sxs4[Nn];        // positions, padded float4 (4 KB)
    __shared__ float    s_wpart[16][4];
    __shared__ unsigned s_tk;
    __shared__ float    s_m[4];

    const float hstep    = DMAXf / (float)KI;
    const float inv_step = (float)KI / DMAXf;

    const int b     = blk >> 2;
    const int ibase = (blk & 3) * 64;

    // =========================== Phase A: table ===========================
    {
        if (tid < Nn) {
            const float* xb = x + b * Nn * 3 + tid * 3;
            sxs4[tid] = make_float4(xb[0], xb[1], xb[2], 0.f);
        }

        // stage W2: 1024 float4 over 512 threads -> 2 each
        reinterpret_cast<float4*>(sW2)[tid]       = reinterpret_cast<const float4*>(W2)[tid];
        reinterpret_cast<float4*>(sW2)[tid + 512] = reinterpret_cast<const float4*>(W2)[tid + 512];

        const int slot = tid >> 6;        // 0..7; slots 0..4 active
        const int p    = tid & 63;
        const int node = blk * 4 + slot;
        const float t  = t_in[0];
        const float d  = (float)node * hstep;

        if (slot < 5) {
            float w0 = W1[p];
            float z  = fmaf(d, w0, fmaf(t, W1[64 + p], b1[p]));
            float h1 = fast_tanh(z);
            float e1 = 1.f - h1 * h1;
            sh1[slot][p] = make_float2(h1, e1 * w0);
        }
        __syncthreads();

        float pf = 0.f, pfp = 0.f;
        if (slot < 5) {
            float s  = b2[p];
            float sd = 0.f;
#pragma unroll 8
            for (int l = 0; l < Hn; l++) {
                float  w2 = sW2[l * 64 + p];
                float2 hv = sh1[slot][l];
                s  = fmaf(w2, hv.x, s);
                sd = fmaf(w2, hv.y, sd);
            }
            float h2 = fast_tanh(s);
            float e2 = 1.f - h2 * h2;
            float w3 = W3[p];
            pf  = w3 * h2;
            pfp = w3 * e2 * sd;
        }

        const unsigned FULL = 0xffffffffu;
#pragma unroll
        for (int off = 16; off; off >>= 1) {
            pf  += __shfl_down_sync(FULL, pf,  off);
            pfp += __shfl_down_sync(FULL, pfp, off);
        }
        if (slot < 5 && (p & 31) == 0) {
            int ws = p >> 5;
            s_red[slot][ws][0] = pf;
            s_red[slot][ws][1] = pfp;
        }
        __syncthreads();
        if (slot < 5 && p == 0) {
            s_node[slot] = make_float2(
                s_red[slot][0][0] + s_red[slot][1][0] + b3[0],
                s_red[slot][0][1] + s_red[slot][1][1]);
        }
        __syncthreads();

        if (tid < 4) {
            float2 n0 = s_node[tid];
            float2 n1 = s_node[tid + 1];
            float P0 = n0.x, P1 = n1.x;
            float M0 = hstep * n0.y, M1 = hstep * n1.y;
            g_tab[blk * 4 + tid] = make_float4(
                P0, M0,
                3.f * (P1 - P0) - 2.f * M0 - M1,
                2.f * (P0 - P1) + M0 + M1);
        }
    }

    grid_barrier0();

    stab[tid] = g_tab[tid];              // 512 float4, coalesced
    __syncthreads();

    // =========================== Phase B: pairs ===========================
    // 16 warps; warp w owns 4 particles: ibase + w + {0,16,32,48}
    const int w    = tid >> 5;
    const int lane = tid & 31;
    const int iA   = ibase + w;
    const int iB   = iA + 16;
    const int iC   = iA + 32;
    const int iD   = iA + 48;

    {
        const float4 XA = sxs4[iA];
        const float4 XB = sxs4[iB];
        const float4 XC = sxs4[iC];
        const float4 XD = sxs4[iD];

        float cA0 = 0.f, cA1 = 0.f, cA2 = 0.f, sTA = 0.f;
        float cB0 = 0.f, cB1 = 0.f, cB2 = 0.f, sTB = 0.f;
        float cC0 = 0.f, cC1 = 0.f, cC2 = 0.f, sTC = 0.f;
        float cD0 = 0.f, cD1 = 0.f, cD2 = 0.f, sTD = 0.f;

#pragma unroll
        for (int jj = 0; jj < 8; jj++) {
            int j = jj * 32 + lane;
            float4 XJ = sxs4[j];
            PAIR_BODY(XA, iA, cA0, cA1, cA2, sTA)
            PAIR_BODY(XB, iB, cB0, cB1, cB2, sTB)
            PAIR_BODY(XC, iC, cC0, cC1, cC2, sTC)
            PAIR_BODY(XD, iD, cD0, cD1, cD2, sTD)
        }

        const unsigned FULL = 0xffffffffu;
#pragma unroll
        for (int off = 16; off; off >>= 1) {
            cA0 += __shfl_down_sync(FULL, cA0, off);
            cA1 += __shfl_down_sync(FULL, cA1, off);
            cA2 += __shfl_down_sync(FULL, cA2, off);
            sTA += __shfl_down_sync(FULL, sTA, off);
            cB0 += __shfl_down_sync(FULL, cB0, off);
            cB1 += __shfl_down_sync(FULL, cB1, off);
            cB2 += __shfl_down_sync(FULL, cB2, off);
            sTB += __shfl_down_sync(FULL, sTB, off);
            cC0 += __shfl_down_sync(FULL, cC0, off);
            cC1 += __shfl_down_sync(FULL, cC1, off);
            cC2 += __shfl_down_sync(FULL, cC2, off);
            sTC += __shfl_down_sync(FULL, sTC, off);
            cD0 += __shfl_down_sync(FULL, cD0, off);
            cD1 += __shfl_down_sync(FULL, cD1, off);
            cD2 += __shfl_down_sync(FULL, cD2, off);
            sTD += __shfl_down_sync(FULL, sTD, off);
        }

        if (lane == 0) {
            const float invNm1 = 1.f / (float)(Nn - 1);
            float vA0 = cA0 * invNm1, vA1 = cA1 * invNm1, vA2 = cA2 * invNm1;
            float vB0 = cB0 * invNm1, vB1 = cB1 * invNm1, vB2 = cB2 * invNm1;
            float vC0 = cC0 * invNm1, vC1 = cC1 * invNm1, vC2 = cC2 * invNm1;
            float vD0 = cD0 * invNm1, vD1 = cD1 * invNm1, vD2 = cD2 * invNm1;
            float tS  = (sTA + sTB + sTC + sTD) * invNm1;

            float* gv = g_v + (b * Nn) * 3;
            gv[iA * 3 + 0] = vA0; gv[iA * 3 + 1] = vA1; gv[iA * 3 + 2] = vA2;
            gv[iB * 3 + 0] = vB0; gv[iB * 3 + 1] = vB1; gv[iB * 3 + 2] = vB2;
            gv[iC * 3 + 0] = vC0; gv[iC * 3 + 1] = vC1; gv[iC * 3 + 2] = vC2;
            gv[iD * 3 + 0] = vD0; gv[iD * 3 + 1] = vD1; gv[iD * 3 + 2] = vD2;

            s_wpart[w][0] = vA0 + vB0 + vC0 + vD0;
            s_wpart[w][1] = vA1 + vB1 + vC1 + vD1;
            s_wpart[w][2] = vA2 + vB2 + vC2 + vD2;
            s_wpart[w][3] = tS;
        }
        __syncthreads();
        if (tid < 4) {
            float acc = 0.f;
#pragma unroll
            for (int ww = 0; ww < 16; ww++) acc += s_wpart[ww][tid];
            atomicAdd(&g_bsum[b * 4 + tid], acc);
        }
        __syncthreads();
    }

    // ===== per-batch ticket: 4th arriver finalizes this batch =====
    if (tid == 0) {
        __threadfence();
        s_tk = atomicAdd(&g_ticket[b], 1u);
        if (s_tk == 3) __threadfence();
    }
    __syncthreads();

    if (s_tk == 3) {
        if (tid < 4) s_m[tid] = g_bsum[b * 4 + tid];
        __syncthreads();

        const float invN = 1.f / (float)Nn;
        const float m0 = s_m[0] * invN;
        const float m1 = s_m[1] * invN;
        const float m2 = s_m[2] * invN;

        for (int idx = tid; idx < Nn * 3; idx += NT) {
            int c = idx - (idx / 3) * 3;
            float mm = (c == 0) ? m0 : ((c == 1) ? m1 : m2);
            out[b * (Nn * 3) + idx] = g_v[b * (Nn * 3) + idx] - mm;
        }
        if (tid == 0)
            out[Bn * Nn * 3 + b] = s_m[3] * (1.f - 1.f / (float)Nn);

        __syncthreads();
        if (tid < 4) g_bsum[b * 4 + tid] = 0.f;
        if (tid == 0) g_ticket[b] = 0u;
    }
}

// ---------------------------------------------------------------------------
extern "C" void kernel_launch(void* const* d_in, const int* in_sizes, int n_in,
                              void* d_out, int out_size)
{
    const float* t  = (const float*)d_in[0];
    const float* x  = (const float*)d_in[1];
    const float* W1 = (const float*)d_in[2];
    const float* b1 = (const float*)d_in[3];
    const float* W2 = (const float*)d_in[4];
    const float* b2 = (const float*)d_in[5];
    const float* W3 = (const float*)d_in[6];
    const float* b3 = (const float*)d_in[7];

    fused_kernel<<<NB, NT>>>(t, x, W1, b1, W2, b2, W3, b3, (float*)d_out);
}

// round 11
// speedup vs baseline: 1.0079x; 1.0059x over previous
#include <cuda_runtime.h>
#include <math.h>

// Problem constants
#define Bn   32
#define Nn   256
#define Hn   64
#define EPSf 1e-6f

// Table: KI intervals in d over [0, DMAX]; one float4 f-cubic each (power basis).
#define KI    256
#define DMAXf 20.0f

// Persistent shape: 128 blocks x 1024 threads (proven best)
#define NB 128
#define NT 1024

// Device scratch (zero-init; restored each launch -> graph-replay safe)
__device__ float4   g_tab[KI];
__device__ float    g_v[Bn * Nn * 3];
__device__ float    g_bsum[Bn * 4];
__device__ unsigned g_ticket[Bn];
__device__ unsigned g_bar_cnt;
__device__ unsigned g_bar_gen;

__device__ __forceinline__ void grid_barrier0()
{
    __syncthreads();
    if (threadIdx.x == 0) {
        __threadfence();
        volatile unsigned* genp = &g_bar_gen;
        unsigned gen = *genp;
        unsigned tkt = atomicAdd(&g_bar_cnt, 1u);
        if (tkt == NB - 1) {
            atomicExch(&g_bar_cnt, 0u);
            __threadfence();
            atomicAdd(&g_bar_gen, 1u);
        } else {
            while (*genp == gen) { __nanosleep(64); }
        }
        __threadfence();
    }
    __syncthreads();
}

__device__ __forceinline__ float fast_tanh(float z)
{
    float az = fabsf(z);
    float e  = __expf(-2.f * az);
    float t  = __fdividef(1.f - e, 1.f + e);
    return copysignf(t, z);
}

// Maskless pair body: self pair (r=0) contributes 0 to field automatically and
// exactly 3*f(sqrt(eps)) to trace (corrected once after the loop).
#define PAIR_BODY(XI, c0, c1, c2, st)                                        \
    {                                                                        \
        float r0 = XI.x - XJ.x, r1 = XI.y - XJ.y, r2 = XI.z - XJ.z;          \
        float d2   = fmaf(r0, r0, fmaf(r1, r1, fmaf(r2, r2, EPSf)));         \
        float rinv = rsqrtf(d2);                                             \
        float u = fminf(d2 * rinv * inv_step, UMAXf);                        \
        int   k = (int)u;                                                    \
        float wf = u - (float)k;                                             \
        float4 A = stab[k];                                                  \
        float q   = fmaf(A.w, wf, A.z);                                      \
        float f   = fmaf(fmaf(q, wf, A.y), wf, A.x);                         \
        float fpw = fmaf(fmaf(A.w, wf, q + q), wf, A.y);                     \
        c0 = fmaf(r0, f, c0);                                                \
        c1 = fmaf(r1, f, c1);                                                \
        c2 = fmaf(r2, f, c2);                                                \
        st = st + fmaf(fpw * inv_step * (d2 - EPSf), rinv, 3.f * f);         \
    }

// ---------------------------------------------------------------------------
__global__ void __launch_bounds__(NT, 1)
fused_kernel(const float* __restrict__ t_in,
             const float* __restrict__ x,
             const float* __restrict__ W1,   // (2,64)
             const float* __restrict__ b1,   // (64)
             const float* __restrict__ W2,   // (64,64)
             const float* __restrict__ b2,   // (64)
             const float* __restrict__ W3,   // (64,1)
             const float* __restrict__ b3,   // (1)
             float*       __restrict__ out)
{
    const int tid = threadIdx.x;
    const int blk = blockIdx.x;

    __shared__ float    sW2[Hn * Hn];    // 16 KB (phase A)
    __shared__ float4   stab[KI];        // 4 KB  (phase B table)
    __shared__ float2   sh1[3][Hn];
    __shared__ float2   s_node[4];
    __shared__ float    s_red[3][2][2];
    __shared__ float4   sxs4[Nn];        // positions, padded float4
    __shared__ float    s_wpart[32][4];
    __shared__ unsigned s_tk;
    __shared__ float    s_m[4];

    const float hstep    = DMAXf / (float)KI;
    const float inv_step = (float)KI / DMAXf;
    const float UMAXf    = (float)KI - 0.001f;

    const int b     = blk >> 2;
    const int ibase = (blk & 3) * 64;

    // =========================== Phase A: table ===========================
    // Block owns intervals 2*blk, 2*blk+1 -> nodes 2*blk .. 2*blk+2 (3 slots).
    {
        if (tid < Nn) {
            const float* xb = x + b * Nn * 3 + tid * 3;
            sxs4[tid] = make_float4(xb[0], xb[1], xb[2], 0.f);
        }

        reinterpret_cast<float4*>(sW2)[tid] =
            reinterpret_cast<const float4*>(W2)[tid];

        const int slot = tid >> 6;        // 0..15; slots 0..2 active
        const int p    = tid & 63;
        const int node = blk * 2 + slot;  // max 127*2+2 = 256 ✓
        const float t  = t_in[0];
        const float d  = (float)node * hstep;

        if (slot < 3) {
            float w0 = W1[p];
            float z  = fmaf(d, w0, fmaf(t, W1[64 + p], b1[p]));
            float h1 = fast_tanh(z);
            float e1 = 1.f - h1 * h1;
            sh1[slot][p] = make_float2(h1, e1 * w0);
        }
        __syncthreads();

        float pf = 0.f, pfp = 0.f;
        if (slot < 3) {
            float s  = b2[p];
            float sd = 0.f;
#pragma unroll 8
            for (int l = 0; l < Hn; l++) {
                float  w2 = sW2[l * 64 + p];
                float2 hv = sh1[slot][l];
                s  = fmaf(w2, hv.x, s);
                sd = fmaf(w2, hv.y, sd);
            }
            float h2 = fast_tanh(s);
            float e2 = 1.f - h2 * h2;
            float w3 = W3[p];
            pf  = w3 * h2;
            pfp = w3 * e2 * sd;
        }

        const unsigned FULL = 0xffffffffu;
#pragma unroll
        for (int off = 16; off; off >>= 1) {
            pf  += __shfl_down_sync(FULL, pf,  off);
            pfp += __shfl_down_sync(FULL, pfp, off);
        }
        if (slot < 3 && (p & 31) == 0) {
            int ws = p >> 5;
            s_red[slot][ws][0] = pf;
            s_red[slot][ws][1] = pfp;
        }
        __syncthreads();
        if (slot < 3 && p == 0) {
            s_node[slot] = make_float2(
                s_red[slot][0][0] + s_red[slot][1][0] + b3[0],
                s_red[slot][0][1] + s_red[slot][1][1]);
        }
        __syncthreads();

        if (tid < 2) {
            float2 n0 = s_node[tid];
            float2 n1 = s_node[tid + 1];
            float P0 = n0.x, P1 = n1.x;
            float M0 = hstep * n0.y, M1 = hstep * n1.y;
            g_tab[blk * 2 + tid] = make_float4(
                P0, M0,
                3.f * (P1 - P0) - 2.f * M0 - M1,
                2.f * (P0 - P1) + M0 + M1);
        }
    }

    grid_barrier0();

    if (tid < KI) stab[tid] = g_tab[tid];   // 256 float4, coalesced
    __syncthreads();

    // =========================== Phase B: pairs ===========================
    const int w    = tid >> 5;
    const int lane = tid & 31;
    const int iA   = ibase + w;
    const int iB   = iA + 32;

    {
        const float4 XA = sxs4[iA];
        const float4 XB = sxs4[iB];

        float cA0 = 0.f, cA1 = 0.f, cA2 = 0.f, sTA = 0.f;
        float cB0 = 0.f, cB1 = 0.f, cB2 = 0.f, sTB = 0.f;

#pragma unroll
        for (int jj = 0; jj < 8; jj++) {
            int j = jj * 32 + lane;
            float4 XJ = sxs4[j];
            PAIR_BODY(XA, cA0, cA1, cA2, sTA)
            PAIR_BODY(XB, cB0, cB1, cB2, sTB)
        }

        const unsigned FULL = 0xffffffffu;
#pragma unroll
        for (int off = 16; off; off >>= 1) {
            cA0 += __shfl_down_sync(FULL, cA0, off);
            cA1 += __shfl_down_sync(FULL, cA1, off);
            cA2 += __shfl_down_sync(FULL, cA2, off);
            sTA += __shfl_down_sync(FULL, sTA, off);
            cB0 += __shfl_down_sync(FULL, cB0, off);
            cB1 += __shfl_down_sync(FULL, cB1, off);
            cB2 += __shfl_down_sync(FULL, cB2, off);
            sTB += __shfl_down_sync(FULL, sTB, off);
        }

        if (lane == 0) {
            // self-pair trace correction: exactly 3*f(sqrt(eps)) per i.
            // Same table eval as in-loop -> exact cancellation.
            float us = fminf(sqrtf(EPSf) * inv_step, UMAXf);
            int   ks = (int)us;
            float ws2 = us - (float)ks;
            float4 As = stab[ks];
            float qs = fmaf(As.w, ws2, As.z);
            float fs = fmaf(fmaf(qs, ws2, As.y), ws2, As.x);
            sTA -= 3.f * fs;
            sTB -= 3.f * fs;

            const float invNm1 = 1.f / (float)(Nn - 1);
            float vA0 = cA0 * invNm1, vA1 = cA1 * invNm1, vA2 = cA2 * invNm1;
            float vB0 = cB0 * invNm1, vB1 = cB1 * invNm1, vB2 = cB2 * invNm1;
            float tAB = (sTA + sTB) * invNm1;

            int rA = b * Nn + iA;
            int rB = b * Nn + iB;
            g_v[rA * 3 + 0] = vA0;
            g_v[rA * 3 + 1] = vA1;
            g_v[rA * 3 + 2] = vA2;
            g_v[rB * 3 + 0] = vB0;
            g_v[rB * 3 + 1] = vB1;
            g_v[rB * 3 + 2] = vB2;

            s_wpart[w][0] = vA0 + vB0;
            s_wpart[w][1] = vA1 + vB1;
            s_wpart[w][2] = vA2 + vB2;
            s_wpart[w][3] = tAB;
        }
        __syncthreads();
        if (tid < 4) {
            float acc = 0.f;
#pragma unroll
            for (int ww = 0; ww < 32; ww++) acc += s_wpart[ww][tid];
            atomicAdd(&g_bsum[b * 4 + tid], acc);
        }
        __syncthreads();
    }

    // ===== per-batch ticket: 4th arriver finalizes this batch =====
    if (tid == 0) {
        __threadfence();
        s_tk = atomicAdd(&g_ticket[b], 1u);
        if (s_tk == 3) __threadfence();
    }
    __syncthreads();

    if (s_tk == 3) {
        if (tid < 4) s_m[tid] = g_bsum[b * 4 + tid];
        __syncthreads();

        const float invN = 1.f / (float)Nn;
        const float m0 = s_m[0] * invN;
        const float m1 = s_m[1] * invN;
        const float m2 = s_m[2] * invN;

        if (tid < Nn * 3) {
            int c = tid - (tid / 3) * 3;
            float mm = (c == 0) ? m0 : ((c == 1) ? m1 : m2);
            out[b * (Nn * 3) + tid] = g_v[b * (Nn * 3) + tid] - mm;
        }
        if (tid == 0)
            out[Bn * Nn * 3 + b] = s_m[3] * (1.f - 1.f / (float)Nn);

        __syncthreads();
        if (tid < 4) g_bsum[b * 4 + tid] = 0.f;
        if (tid == 0) g_ticket[b] = 0u;
    }
}

// ---------------------------------------------------------------------------
extern "C" void kernel_launch(void* const* d_in, const int* in_sizes, int n_in,
                              void* d_out, int out_size)
{
    const float* t  = (const float*)d_in[0];
    const float* x  = (const float*)d_in[1];
    const float* W1 = (const float*)d_in[2];
    const float* b1 = (const float*)d_in[3];
    const float* W2 = (const float*)d_in[4];
    const float* b2 = (const float*)d_in[5];
    const float* W3 = (const float*)d_in[6];
    const float* b3 = (const float*)d_in[7];

    fused_kernel<<<NB, NT>>>(t, x, W1, b1, W2, b2, W3, b3, (float*)d_out);
}

// round 12
// speedup vs baseline: 1.0599x; 1.0517x over previous
#include <cuda_runtime.h>
#include <math.h>

// Problem constants
#define Bn   32
#define Nn   256
#define Hn   64
#define EPSf 1e-6f

// Table: KI intervals in d over [0, DMAX]; one float4 f-cubic each (power basis).
#define KI    256
#define DMAXf 20.0f

// Persistent shape: 128 blocks x 1024 threads (proven best)
#define NB 128
#define NT 1024

#define MAGICf 8388608.0f   // 2^23; bit pattern 0x4B000000

// Device scratch (zero-init; restored each launch -> graph-replay safe)
__device__ float4   g_tab[KI];
__device__ float    g_v[Bn * Nn * 3];
__device__ float    g_bsum[Bn * 4];
__device__ unsigned g_ticket[Bn];
__device__ unsigned g_bar_cnt;
__device__ unsigned g_bar_gen;

__device__ __forceinline__ void grid_barrier0()
{
    __syncthreads();
    if (threadIdx.x == 0) {
        __threadfence();
        volatile unsigned* genp = &g_bar_gen;
        unsigned gen = *genp;
        unsigned tkt = atomicAdd(&g_bar_cnt, 1u);
        if (tkt == NB - 1) {
            atomicExch(&g_bar_cnt, 0u);
            __threadfence();
            atomicAdd(&g_bar_gen, 1u);
        } else {
            while (*genp == gen) { __nanosleep(64); }
        }
        __threadfence();
    }
    __syncthreads();
}

__device__ __forceinline__ float fast_tanh(float z)
{
    float az = fabsf(z);
    float e  = __expf(-2.f * az);
    float t  = __fdividef(1.f - e, 1.f + e);
    return copysignf(t, z);
}

// Maskless pair body with magic-float floor (no F2I/I2F on the chain).
// Self pair (r=0): field FMAs add 0; trace adds exactly 3*f(u_self),
// corrected after the loop with a bitwise-identical evaluation.
#define PAIR_BODY(XI, c0, c1, c2, st)                                        \
    {                                                                        \
        float r0 = XI.x - XJ.x, r1 = XI.y - XJ.y, r2 = XI.z - XJ.z;          \
        float d2   = fmaf(r0, r0, fmaf(r1, r1, fmaf(r2, r2, EPSf)));         \
        float rinv = rsqrtf(d2);                                             \
        float du   = d2 * inv_step;            /* overlaps MUFU.RSQ */       \
        float u    = fminf(du * rinv, UMAXf);                                \
        float uf   = __fadd_rz(u, MAGICf);     /* 2^23 + floor(u), exact */  \
        int   k    = __float_as_int(uf) & 0x7FFFFF;                          \
        float wf   = u - (uf - MAGICf);                                      \
        float4 A   = stab[k];                                                \
        float q    = fmaf(A.w, wf, A.z);                                     \
        float f    = fmaf(fmaf(q, wf, A.y), wf, A.x);                        \
        float fpw  = fmaf(fmaf(A.w, wf, q + q), wf, A.y);                    \
        c0 = fmaf(r0, f, c0);                                                \
        c1 = fmaf(r1, f, c1);                                                \
        c2 = fmaf(r2, f, c2);                                                \
        st = st + fmaf(fpw * inv_step * (d2 - EPSf), rinv, 3.f * f);         \
    }

// ---------------------------------------------------------------------------
__global__ void __launch_bounds__(NT, 1)
fused_kernel(const float* __restrict__ t_in,
             const float* __restrict__ x,
             const float* __restrict__ W1,   // (2,64)
             const float* __restrict__ b1,   // (64)
             const float* __restrict__ W2,   // (64,64)
             const float* __restrict__ b2,   // (64)
             const float* __restrict__ W3,   // (64,1)
             const float* __restrict__ b3,   // (1)
             float*       __restrict__ out)
{
    const int tid = threadIdx.x;
    const int blk = blockIdx.x;

    __shared__ float    sW2[Hn * Hn];    // 16 KB (phase A)
    __shared__ float4   stab[KI];        // 4 KB  (phase B table)
    __shared__ float2   sh1[3][Hn];
    __shared__ float2   s_node[4];
    __shared__ float    s_red[3][2][2];
    __shared__ float4   sxs4[Nn];        // positions, padded float4
    __shared__ float    s_wpart[32][4];
    __shared__ unsigned s_tk;
    __shared__ float    s_m[4];

    const float hstep    = DMAXf / (float)KI;
    const float inv_step = (float)KI / DMAXf;
    const float UMAXf    = (float)KI - 0.001f;

    const int b     = blk >> 2;
    const int ibase = (blk & 3) * 64;

    // =========================== Phase A: table ===========================
    // Block owns intervals 2*blk, 2*blk+1 -> nodes 2*blk .. 2*blk+2.
    {
        if (tid < Nn) {
            const float* xb = x + b * Nn * 3 + tid * 3;
            sxs4[tid] = make_float4(xb[0], xb[1], xb[2], 0.f);
        }

        reinterpret_cast<float4*>(sW2)[tid] =
            reinterpret_cast<const float4*>(W2)[tid];

        const int slot = tid >> 6;        // 0..15; slots 0..2 active
        const int p    = tid & 63;
        const int node = blk * 2 + slot;
        const float t  = t_in[0];
        const float d  = (float)node * hstep;

        if (slot < 3) {
            float w0 = W1[p];
            float z  = fmaf(d, w0, fmaf(t, W1[64 + p], b1[p]));
            float h1 = fast_tanh(z);
            float e1 = 1.f - h1 * h1;
            sh1[slot][p] = make_float2(h1, e1 * w0);
        }
        __syncthreads();

        float pf = 0.f, pfp = 0.f;
        if (slot < 3) {
            float s  = b2[p];
            float sd = 0.f;
#pragma unroll 8
            for (int l = 0; l < Hn; l++) {
                float  w2 = sW2[l * 64 + p];
                float2 hv = sh1[slot][l];
                s  = fmaf(w2, hv.x, s);
                sd = fmaf(w2, hv.y, sd);
            }
            float h2 = fast_tanh(s);
            float e2 = 1.f - h2 * h2;
            float w3 = W3[p];
            pf  = w3 * h2;
            pfp = w3 * e2 * sd;
        }

        const unsigned FULL = 0xffffffffu;
#pragma unroll
        for (int off = 16; off; off >>= 1) {
            pf  += __shfl_down_sync(FULL, pf,  off);
            pfp += __shfl_down_sync(FULL, pfp, off);
        }
        if (slot < 3 && (p & 31) == 0) {
            int ws = p >> 5;
            s_red[slot][ws][0] = pf;
            s_red[slot][ws][1] = pfp;
        }
        __syncthreads();
        if (slot < 3 && p == 0) {
            s_node[slot] = make_float2(
                s_red[slot][0][0] + s_red[slot][1][0] + b3[0],
                s_red[slot][0][1] + s_red[slot][1][1]);
        }
        __syncthreads();

        if (tid < 2) {
            float2 n0 = s_node[tid];
            float2 n1 = s_node[tid + 1];
            float P0 = n0.x, P1 = n1.x;
            float M0 = hstep * n0.y, M1 = hstep * n1.y;
            g_tab[blk * 2 + tid] = make_float4(
                P0, M0,
                3.f * (P1 - P0) - 2.f * M0 - M1,
                2.f * (P0 - P1) + M0 + M1);
        }
    }

    grid_barrier0();

    if (tid < KI) stab[tid] = g_tab[tid];   // 256 float4, coalesced
    __syncthreads();

    // =========================== Phase B: pairs ===========================
    const int w    = tid >> 5;
    const int lane = tid & 31;
    const int iA   = ibase + w;
    const int iB   = iA + 32;

    {
        const float4 XA = sxs4[iA];
        const float4 XB = sxs4[iB];

        float cA0 = 0.f, cA1 = 0.f, cA2 = 0.f, sTA = 0.f;
        float cB0 = 0.f, cB1 = 0.f, cB2 = 0.f, sTB = 0.f;

        float4 XJ = sxs4[lane];              // prefetch jj = 0
#pragma unroll
        for (int jj = 0; jj < 8; jj++) {
            float4 XJn;
            if (jj < 7) XJn = sxs4[(jj + 1) * 32 + lane];   // prefetch next
            PAIR_BODY(XA, cA0, cA1, cA2, sTA)
            PAIR_BODY(XB, cB0, cB1, cB2, sTB)
            XJ = XJn;
        }

        const unsigned FULL = 0xffffffffu;
#pragma unroll
        for (int off = 16; off; off >>= 1) {
            cA0 += __shfl_down_sync(FULL, cA0, off);
            cA1 += __shfl_down_sync(FULL, cA1, off);
            cA2 += __shfl_down_sync(FULL, cA2, off);
            sTA += __shfl_down_sync(FULL, sTA, off);
            cB0 += __shfl_down_sync(FULL, cB0, off);
            cB1 += __shfl_down_sync(FULL, cB1, off);
            cB2 += __shfl_down_sync(FULL, cB2, off);
            sTB += __shfl_down_sync(FULL, sTB, off);
        }

        if (lane == 0) {
            // Self-pair trace correction: bitwise-identical re-evaluation of
            // the in-loop expression at d2 = EPSf, then subtract 3*f once.
            float rinvs = rsqrtf(EPSf);
            float us  = fminf((EPSf * inv_step) * rinvs, UMAXf);
            float ufs = __fadd_rz(us, MAGICf);
            int   ks  = __float_as_int(ufs) & 0x7FFFFF;
            float wfs = us - (ufs - MAGICf);
            float4 As = stab[ks];
            float qs  = fmaf(As.w, wfs, As.z);
            float fs  = fmaf(fmaf(qs, wfs, As.y), wfs, As.x);
            sTA -= 3.f * fs;
            sTB -= 3.f * fs;

            const float invNm1 = 1.f / (float)(Nn - 1);
            float vA0 = cA0 * invNm1, vA1 = cA1 * invNm1, vA2 = cA2 * invNm1;
            float vB0 = cB0 * invNm1, vB1 = cB1 * invNm1, vB2 = cB2 * invNm1;
            float tAB = (sTA + sTB) * invNm1;

            int rA = b * Nn + iA;
            int rB = b * Nn + iB;
            g_v[rA * 3 + 0] = vA0;
            g_v[rA * 3 + 1] = vA1;
            g_v[rA * 3 + 2] = vA2;
            g_v[rB * 3 + 0] = vB0;
            g_v[rB * 3 + 1] = vB1;
            g_v[rB * 3 + 2] = vB2;

            s_wpart[w][0] = vA0 + vB0;
            s_wpart[w][1] = vA1 + vB1;
            s_wpart[w][2] = vA2 + vB2;
            s_wpart[w][3] = tAB;
        }
        __syncthreads();
        if (tid < 4) {
            float acc = 0.f;
#pragma unroll
            for (int ww = 0; ww < 32; ww++) acc += s_wpart[ww][tid];
            atomicAdd(&g_bsum[b * 4 + tid], acc);
        }
        __syncthreads();
    }

    // ===== per-batch ticket: 4th arriver finalizes this batch =====
    if (tid == 0) {
        __threadfence();
        s_tk = atomicAdd(&g_ticket[b], 1u);
        if (s_tk == 3) __threadfence();
    }
    __syncthreads();

    if (s_tk == 3) {
        if (tid < 4) s_m[tid] = g_bsum[b * 4 + tid];
        __syncthreads();

        const float invN = 1.f / (float)Nn;
        const float m0 = s_m[0] * invN;
        const float m1 = s_m[1] * invN;
        const float m2 = s_m[2] * invN;

        if (tid < Nn * 3) {
            int c = tid - (tid / 3) * 3;
            float mm = (c == 0) ? m0 : ((c == 1) ? m1 : m2);
            out[b * (Nn * 3) + tid] = g_v[b * (Nn * 3) + tid] - mm;
        }
        if (tid == 0)
            out[Bn * Nn * 3 + b] = s_m[3] * (1.f - 1.f / (float)Nn);

        __syncthreads();
        if (tid < 4) g_bsum[b * 4 + tid] = 0.f;
        if (tid == 0) g_ticket[b] = 0u;
    }
}

// ---------------------------------------------------------------------------
extern "C" void kernel_launch(void* const* d_in, const int* in_sizes, int n_in,
                              void* d_out, int out_size)
{
    const float* t  = (const float*)d_in[0];
    const float* x  = (const float*)d_in[1];
    const float* W1 = (const float*)d_in[2];
    const float* b1 = (const float*)d_in[3];
    const float* W2 = (const float*)d_in[4];
    const float* b2 = (const float*)d_in[5];
    const float* W3 = (const float*)d_in[6];
    const float* b3 = (const float*)d_in[7];

    fused_kernel<<<NB, NT>>>(t, x, W1, b1, W2, b2, W3, b3, (float*)d_out);
}